// round 1
// baseline (speedup 1.0000x reference)
#include <cuda_runtime.h>
#include <cuda_fp16.h>
#include <mma.h>
#include <cstdint>
#include <cstddef>

using namespace nvcuda;

// Problem dims
#define B_SZ   65536
#define F_DIM  1024
#define H_N    16
#define D_H    64
#define NQKV   3072
#define OUT_N  1024
#define K_DIM  1024

// ---------------------------------------------------------------------------
// Scratch (allocation-free: __device__ globals)
// ---------------------------------------------------------------------------
__device__ __half g_xh  [(size_t)B_SZ * F_DIM];    // x in fp16            128 MB
__device__ __half g_wqkv[(size_t)F_DIM * NQKV];    // packed Wq|Wk|Wv        6 MB
__device__ __half g_wf  [(size_t)F_DIM * OUT_N];   // Wf fp16                2 MB
__device__ __half g_qkv [(size_t)B_SZ * NQKV];     // QKV = x @ Wqkv       384 MB
__device__ __half g_c   [(size_t)B_SZ * F_DIM];    // transposed concat    128 MB

// ---------------------------------------------------------------------------
// Converters
// ---------------------------------------------------------------------------
__global__ void convert_x_kernel(const float4* __restrict__ x) {
    const size_t n4 = (size_t)B_SZ * F_DIM / 4;
    __half2* out = reinterpret_cast<__half2*>(g_xh);
    for (size_t i = (size_t)blockIdx.x * blockDim.x + threadIdx.x; i < n4;
         i += (size_t)gridDim.x * blockDim.x) {
        float4 v = x[i];
        out[2 * i]     = __floats2half2_rn(v.x, v.y);
        out[2 * i + 1] = __floats2half2_rn(v.z, v.w);
    }
}

// Pack Wq/Wk/Wv [H,F,D] into B-matrix [F][3072] with col = which*1024 + h*64 + d
__global__ void convert_wqkv_kernel(const float* __restrict__ Wq,
                                    const float* __restrict__ Wk,
                                    const float* __restrict__ Wv) {
    const int total = F_DIM * NQKV;
    for (int j = blockIdx.x * blockDim.x + threadIdx.x; j < total;
         j += gridDim.x * blockDim.x) {
        int f = j / NQKV;
        int col = j - f * NQKV;
        int which = col >> 10;
        int hd = col & 1023;
        int h = hd >> 6;
        int d = hd & 63;
        const float* W = (which == 0) ? Wq : ((which == 1) ? Wk : Wv);
        g_wqkv[j] = __float2half(W[((size_t)h * F_DIM + f) * D_H + d]);
    }
}

__global__ void convert_wf_kernel(const float* __restrict__ Wf) {
    const int total = F_DIM * OUT_N;
    for (int j = blockIdx.x * blockDim.x + threadIdx.x; j < total;
         j += gridDim.x * blockDim.x)
        g_wf[j] = __float2half(Wf[j]);
}

// ---------------------------------------------------------------------------
// GEMM: C[M,N] = A[M,K] @ B[K,N], fp16 in, fp32 accumulate.
// CTA tile 128x128, BK=32, 8 warps (2x4), warp tile 64x32, cp.async 2-stage.
// ---------------------------------------------------------------------------
__device__ __forceinline__ void cp_async16(void* smem, const void* gmem) {
    uint32_t s = (uint32_t)__cvta_generic_to_shared(smem);
    asm volatile("cp.async.cg.shared.global [%0], [%1], 16;\n" ::"r"(s), "l"(gmem));
}

template <int N_DIM, bool OUT_HALF, bool BIAS>
__global__ __launch_bounds__(256) void gemm_kernel(
    const __half* __restrict__ A, const __half* __restrict__ Bm,
    __half* __restrict__ Ch, float* __restrict__ Cf,
    const float* __restrict__ bias) {
    constexpr int BM = 128, BN = 128, BK = 32;
    constexpr int LDA = BK + 8;   // 40 halves
    constexpr int LDB = BN + 8;   // 136 halves

    __shared__ __align__(16) __half As[2][BM][LDA];
    __shared__ __align__(16) __half Bs[2][BK][LDB];
    __shared__ float stage[8][256];

    const int tid = threadIdx.x;
    const int warpId = tid >> 5;
    const int lane = tid & 31;
    const int tileM = blockIdx.y * BM;
    const int tileN = blockIdx.x * BN;
    const int wm = warpId >> 2;  // 0..1
    const int wn = warpId & 3;   // 0..3

    wmma::fragment<wmma::accumulator, 16, 16, 16, float> acc[4][2];
#pragma unroll
    for (int i = 0; i < 4; i++)
#pragma unroll
        for (int j = 0; j < 2; j++) wmma::fill_fragment(acc[i][j], 0.0f);

    auto loadTiles = [&](int buf, int k0) {
        // A tile: 128 rows x 32 halves = 512 chunks of 16B
#pragma unroll
        for (int it = 0; it < 2; it++) {
            int c = tid + it * 256;
            int row = c >> 2, seg = c & 3;
            cp_async16(&As[buf][row][seg * 8],
                       A + (size_t)(tileM + row) * K_DIM + k0 + seg * 8);
        }
        // B tile: 32 rows x 128 halves = 512 chunks of 16B
#pragma unroll
        for (int it = 0; it < 2; it++) {
            int c = tid + it * 256;
            int row = c >> 4, seg = c & 15;
            cp_async16(&Bs[buf][row][seg * 8],
                       Bm + (size_t)(k0 + row) * N_DIM + tileN + seg * 8);
        }
        asm volatile("cp.async.commit_group;\n");
    };

    loadTiles(0, 0);
    constexpr int KT = K_DIM / BK;  // 32

    for (int kt = 0; kt < KT; ++kt) {
        if (kt + 1 < KT)
            loadTiles((kt + 1) & 1, (kt + 1) * BK);
        else
            asm volatile("cp.async.commit_group;\n");  // empty group keeps count
        asm volatile("cp.async.wait_group 1;\n");
        __syncthreads();

        const int buf = kt & 1;
#pragma unroll
        for (int kk = 0; kk < BK; kk += 16) {
            wmma::fragment<wmma::matrix_a, 16, 16, 16, __half, wmma::row_major> af[4];
            wmma::fragment<wmma::matrix_b, 16, 16, 16, __half, wmma::row_major> bfr[2];
#pragma unroll
            for (int i = 0; i < 4; i++)
                wmma::load_matrix_sync(af[i], &As[buf][wm * 64 + i * 16][kk], LDA);
#pragma unroll
            for (int j = 0; j < 2; j++)
                wmma::load_matrix_sync(bfr[j], &Bs[buf][kk][wn * 32 + j * 16], LDB);
#pragma unroll
            for (int i = 0; i < 4; i++)
#pragma unroll
                for (int j = 0; j < 2; j++)
                    wmma::mma_sync(acc[i][j], af[i], bfr[j], acc[i][j]);
        }
        __syncthreads();
    }

    // Epilogue: frag -> per-warp smem stage -> (bias) -> global
#pragma unroll
    for (int i = 0; i < 4; i++) {
#pragma unroll
        for (int j = 0; j < 2; j++) {
            wmma::store_matrix_sync(stage[warpId], acc[i][j], 16, wmma::mem_row_major);
            __syncwarp();
#pragma unroll
            for (int p = 0; p < 8; p++) {
                int e = lane + p * 32;
                int r = e >> 4, cc = e & 15;
                int grow = tileM + wm * 64 + i * 16 + r;
                int gcol = tileN + wn * 32 + j * 16 + cc;
                float v = stage[warpId][e];
                if (BIAS) v += bias[gcol];
                if (OUT_HALF)
                    Ch[(size_t)grow * N_DIM + gcol] = __float2half(v);
                else
                    Cf[(size_t)grow * N_DIM + gcol] = v;
            }
            __syncwarp();
        }
    }
}

// ---------------------------------------------------------------------------
// Attention over heads: per row b, q/k/v [16,64] fp16 -> softmax(q k^T / 8) v
// Output transposed concat: c[d*16 + h] = o[h][d], fp16. One warp per row.
// ---------------------------------------------------------------------------
__global__ __launch_bounds__(128) void attn_kernel() {
    __shared__ __align__(16) __half sqkv[4][NQKV];
    __shared__ float ssc[4][256];

    const int w = threadIdx.x >> 5;
    const int lane = threadIdx.x & 31;
    const size_t b = (size_t)blockIdx.x * 4 + w;

    // load qkv row (3072 halves = 384 x 16B)
    const int4* src = reinterpret_cast<const int4*>(g_qkv + b * NQKV);
    int4* dst = reinterpret_cast<int4*>(sqkv[w]);
#pragma unroll
    for (int it = lane; it < 384; it += 32) dst[it] = src[it];
    __syncwarp();

    // scores[h][g] = q_h . k_g / 8
#pragma unroll
    for (int e = lane; e < 256; e += 32) {
        int h = e >> 4, g = e & 15;
        const __half2* qp = reinterpret_cast<const __half2*>(&sqkv[w][h * 64]);
        const __half2* kp = reinterpret_cast<const __half2*>(&sqkv[w][1024 + g * 64]);
        float s = 0.0f;
#pragma unroll
        for (int d2 = 0; d2 < 32; d2++) {
            float2 qf = __half22float2(qp[d2]);
            float2 kf = __half22float2(kp[d2]);
            s = fmaf(qf.x, kf.x, s);
            s = fmaf(qf.y, kf.y, s);
        }
        ssc[w][e] = s * 0.125f;
    }
    __syncwarp();

    // softmax over g for each h (lanes 0..15)
    if (lane < 16) {
        const int h = lane;
        float m = -1e30f;
#pragma unroll
        for (int g = 0; g < 16; g++) m = fmaxf(m, ssc[w][h * 16 + g]);
        float s = 0.0f;
#pragma unroll
        for (int g = 0; g < 16; g++) {
            float e = __expf(ssc[w][h * 16 + g] - m);
            ssc[w][h * 16 + g] = e;
            s += e;
        }
        float inv = 1.0f / s;
#pragma unroll
        for (int g = 0; g < 16; g++) ssc[w][h * 16 + g] *= inv;
    }
    __syncwarp();

    // o[h][d] = sum_g w[h][g] v[g][d];  write c[d*16+h]
    __half* crow = g_c + b * F_DIM;
#pragma unroll
    for (int c = lane; c < 1024; c += 32) {
        int h = c & 15;
        int d = c >> 4;
        float accv = 0.0f;
#pragma unroll
        for (int g = 0; g < 16; g++)
            accv = fmaf(ssc[w][h * 16 + g], __half2float(sqkv[w][2048 + g * 64 + d]), accv);
        crow[c] = __float2half(accv);
    }
}

// ---------------------------------------------------------------------------
// launch
// ---------------------------------------------------------------------------
extern "C" void kernel_launch(void* const* d_in, const int* in_sizes, int n_in,
                              void* d_out, int out_size) {
    const float* x  = (const float*)d_in[0];
    const float* Wq = (const float*)d_in[1];
    const float* Wk = (const float*)d_in[2];
    const float* Wv = (const float*)d_in[3];
    const float* Wf = (const float*)d_in[4];
    const float* bf = (const float*)d_in[5];
    float* out = (float*)d_out;

    void *p_xh = nullptr, *p_wqkv = nullptr, *p_wf = nullptr, *p_qkv = nullptr,
         *p_c = nullptr;
    cudaGetSymbolAddress(&p_xh, g_xh);
    cudaGetSymbolAddress(&p_wqkv, g_wqkv);
    cudaGetSymbolAddress(&p_wf, g_wf);
    cudaGetSymbolAddress(&p_qkv, g_qkv);
    cudaGetSymbolAddress(&p_c, g_c);

    convert_x_kernel<<<16384, 256>>>(reinterpret_cast<const float4*>(x));
    convert_wqkv_kernel<<<3072, 256>>>(Wq, Wk, Wv);
    convert_wf_kernel<<<1024, 256>>>(Wf);

    // QKV = x @ Wqkv   [65536,1024] x [1024,3072]
    gemm_kernel<NQKV, true, false><<<dim3(NQKV / 128, B_SZ / 128), 256>>>(
        (const __half*)p_xh, (const __half*)p_wqkv, (__half*)p_qkv, nullptr,
        nullptr);

    // attention over heads -> transposed concat
    attn_kernel<<<B_SZ / 4, 128>>>();

    // out = concat @ Wf + bf   [65536,1024] x [1024,1024]
    gemm_kernel<OUT_N, false, true><<<dim3(OUT_N / 128, B_SZ / 128), 256>>>(
        (const __half*)p_c, (const __half*)p_wf, nullptr, out, bf);
}

// round 3
// speedup vs baseline: 1.6987x; 1.6987x over previous
#include <cuda_runtime.h>
#include <cuda_fp16.h>
#include <mma.h>
#include <cstdint>
#include <cstddef>

// Problem dims
#define B_SZ   65536
#define F_DIM  1024
#define H_N    16
#define D_H    64
#define NQKV   3072
#define OUT_N  1024
#define K_DIM  1024

#if defined(__CUDA_ARCH_FEAT_SM103_ALL) || defined(__CUDA_ARCH_FEAT_SM100_ALL)
#define HAS_TCGEN05 1
#else
#define HAS_TCGEN05 0
#endif

// ---------------------------------------------------------------------------
// Scratch (allocation-free: __device__ globals)
// ---------------------------------------------------------------------------
__device__ __half g_xh  [(size_t)B_SZ * F_DIM];    // x fp16                128 MB
__device__ __half g_wqkv[(size_t)NQKV * K_DIM];    // packed W^T [3072,1024]  6 MB
__device__ __half g_wf  [(size_t)OUT_N * K_DIM];   // Wf^T [1024,1024]        2 MB
__device__ __half g_qkv [(size_t)B_SZ * NQKV];     // QKV                   384 MB
__device__ __half g_c   [(size_t)B_SZ * F_DIM];    // transposed concat     128 MB

// ---------------------------------------------------------------------------
// PTX helpers (tcgen05 bodies guarded by feature macro)
// ---------------------------------------------------------------------------
__device__ __forceinline__ uint32_t smem_u32(const void* p) {
    return (uint32_t)__cvta_generic_to_shared(p);
}
__device__ __forceinline__ void cp_async16(uint32_t s, const void* g) {
    asm volatile("cp.async.cg.shared.global [%0], [%1], 16;\n" ::"r"(s), "l"(g));
}
__device__ __forceinline__ void mbar_init(uint64_t* b, uint32_t cnt) {
    asm volatile("mbarrier.init.shared.b64 [%0], %1;" ::"r"(smem_u32(b)), "r"(cnt) : "memory");
}
__device__ __forceinline__ void mbar_arrive(uint64_t* b) {
    asm volatile("mbarrier.arrive.shared.b64 _, [%0];" ::"r"(smem_u32(b)) : "memory");
}
__device__ __forceinline__ void mbar_wait(uint64_t* b, uint32_t parity) {
    uint32_t addr = smem_u32(b);
    asm volatile(
        "{\n\t"
        ".reg .pred P1;\n\t"
        "WAIT_LOOP_%=:\n\t"
        "mbarrier.try_wait.parity.acquire.cta.shared::cta.b64 P1, [%0], %1, 0x989680;\n\t"
        "@P1 bra.uni WAIT_DONE_%=;\n\t"
        "bra.uni WAIT_LOOP_%=;\n\t"
        "WAIT_DONE_%=:\n\t"
        "}"
        ::"r"(addr), "r"(parity) : "memory");
}
#if HAS_TCGEN05
__device__ __forceinline__ void tc_commit(uint64_t* b) {
    asm volatile(
        "tcgen05.commit.cta_group::1.mbarrier::arrive::one.shared::cluster.b64 [%0];"
        ::"r"(smem_u32(b)) : "memory");
}
// SW128 K-major smem descriptor: layout=2, version=1, SBO=64, LBO=1
__device__ __forceinline__ uint64_t make_desc(uint32_t addr) {
    constexpr uint64_t BASE =
        (uint64_t(2) << 61) | (uint64_t(1) << 46) | (uint64_t(64) << 32) | (uint64_t(1) << 16);
    return BASE | ((uint64_t)(addr >> 4) & 0x3FFF);
}
__device__ __forceinline__ void mma_f16_ss(uint32_t d, uint64_t a, uint64_t b,
                                           uint32_t idesc, uint32_t en) {
    asm volatile(
        "{\n\t"
        ".reg .pred p;\n\t"
        "setp.ne.u32 p, %5, 0;\n\t"
        "tcgen05.mma.cta_group::1.kind::f16 [%0], %1, %2, %3, {%4, %4, %4, %4}, p;\n\t"
        "}"
        ::"r"(d), "l"(a), "l"(b), "r"(idesc), "r"(0u), "r"(en) : "memory");
}
__device__ __forceinline__ void tmem_ld_x32(uint32_t* r, uint32_t tmem_addr) {
    asm volatile(
        "tcgen05.ld.sync.aligned.32x32b.x32.b32 "
        "{%0, %1, %2, %3, %4, %5, %6, %7, "
        " %8, %9, %10, %11, %12, %13, %14, %15, "
        " %16, %17, %18, %19, %20, %21, %22, %23, "
        " %24, %25, %26, %27, %28, %29, %30, %31}, [%32];"
        : "=r"(r[0]), "=r"(r[1]), "=r"(r[2]), "=r"(r[3]),
          "=r"(r[4]), "=r"(r[5]), "=r"(r[6]), "=r"(r[7]),
          "=r"(r[8]), "=r"(r[9]), "=r"(r[10]), "=r"(r[11]),
          "=r"(r[12]), "=r"(r[13]), "=r"(r[14]), "=r"(r[15]),
          "=r"(r[16]), "=r"(r[17]), "=r"(r[18]), "=r"(r[19]),
          "=r"(r[20]), "=r"(r[21]), "=r"(r[22]), "=r"(r[23]),
          "=r"(r[24]), "=r"(r[25]), "=r"(r[26]), "=r"(r[27]),
          "=r"(r[28]), "=r"(r[29]), "=r"(r[30]), "=r"(r[31])
        : "r"(tmem_addr));
}
#endif  // HAS_TCGEN05

// ---------------------------------------------------------------------------
// Converters
// ---------------------------------------------------------------------------
__global__ void convert_x_kernel(const float4* __restrict__ x) {
    const size_t n4 = (size_t)B_SZ * F_DIM / 4;
    __half2* out = reinterpret_cast<__half2*>(g_xh);
    for (size_t i = (size_t)blockIdx.x * blockDim.x + threadIdx.x; i < n4;
         i += (size_t)gridDim.x * blockDim.x) {
        float4 v = x[i];
        out[2 * i]     = __floats2half2_rn(v.x, v.y);
        out[2 * i + 1] = __floats2half2_rn(v.z, v.w);
    }
}

// Pack Wq/Wk/Wv [H,F,D] into K-major B matrix [3072][1024]: row n = which*1024+h*64+d
__global__ void convert_wqkv_kernel(const float* __restrict__ Wq,
                                    const float* __restrict__ Wk,
                                    const float* __restrict__ Wv) {
    const int total = NQKV * K_DIM;
    for (int j = blockIdx.x * blockDim.x + threadIdx.x; j < total;
         j += gridDim.x * blockDim.x) {
        int n = j >> 10;          // output row (N index)
        int f = j & 1023;         // K index
        int which = n >> 10;
        int hd = n & 1023;
        int h = hd >> 6;
        int d = hd & 63;
        const float* W = (which == 0) ? Wq : ((which == 1) ? Wk : Wv);
        g_wqkv[j] = __float2half(W[((size_t)h * F_DIM + f) * D_H + d]);
    }
}

// Wf [K=1024][N=1024] -> K-major [N][K]
__global__ void convert_wf_kernel(const float* __restrict__ Wf) {
    const int total = OUT_N * K_DIM;
    for (int j = blockIdx.x * blockDim.x + threadIdx.x; j < total;
         j += gridDim.x * blockDim.x) {
        int n = j >> 10;
        int k = j & 1023;
        g_wf[j] = __float2half(Wf[(size_t)k * OUT_N + n]);
    }
}

// ---------------------------------------------------------------------------
// GEMM: C[M,N] = A[M,K] @ W^T, A row-major [M,K] fp16, W K-major [N,K] fp16.
// tcgen05 path: CTA tile 256x256, BK=64, 3-stage cp.async pipeline, TMEM accum.
// Fallback path (no 'a' target): wmma per 128x128 quadrant (round-1 logic).
// ---------------------------------------------------------------------------
#define STAGES 3
#define STAGE_BYTES 65536          // A: 2x16KB halves, B: 32KB
#define SMEM_DYN (STAGES * STAGE_BYTES + 1024)
#define KT 16                      // 1024 / 64

// idesc: dtype=F32(1<<4), atype=btype=F16(0), N=128 -> 16<<17, M=128 -> 8<<24
#define IDESC_F16_128 ((1u << 4) | (16u << 17) | (8u << 24))

template <int N_DIM, bool OUT_HALF, bool BIAS>
__global__ __launch_bounds__(256, 1)
void tc_gemm(const __half* __restrict__ A, const __half* __restrict__ Bw,
             __half* __restrict__ Ch, float* __restrict__ Cf,
             const float* __restrict__ bias) {
    extern __shared__ __align__(16) char dsm[];
    char* tiles = (char*)(((uintptr_t)dsm + 1023) & ~(uintptr_t)1023);

    const int tid = threadIdx.x;
    const int warp = tid >> 5;
    const int lane = tid & 31;
    const size_t tileM = (size_t)blockIdx.y * 256;
    const int tileN = blockIdx.x * 256;

#if HAS_TCGEN05
    __shared__ __align__(8) uint64_t bar_full[STAGES];
    __shared__ __align__(8) uint64_t bar_empty[STAGES];
    __shared__ __align__(8) uint64_t bar_done;
    __shared__ uint32_t s_tmem;

    if (warp == 0) {
        asm volatile(
            "tcgen05.alloc.cta_group::1.sync.aligned.shared::cta.b32 [%0], %1;"
            ::"r"(smem_u32(&s_tmem)), "r"(512) : "memory");
    }
    if (tid == 0) {
        for (int s = 0; s < STAGES; s++) {
            mbar_init(&bar_full[s], 128);
            mbar_init(&bar_empty[s], 1);
        }
        mbar_init(&bar_done, 1);
    }
    __syncthreads();
    const uint32_t tmem = s_tmem;

    if (tid < 128) {
        // ------------------ producer: 128 threads, cp.async ------------------
        int s = 0, ph = 1;  // fresh-barrier: parity-1 wait passes immediately
        for (int kt = 0; kt < KT; kt++) {
            mbar_wait(&bar_empty[s], (uint32_t)ph);
            char* st = tiles + s * STAGE_BYTES;
            const char* Ag = (const char*)(A + tileM * K_DIM + kt * 64);
            const char* Bg = (const char*)(Bw + (size_t)tileN * K_DIM + kt * 64);
#pragma unroll
            for (int i = 0; i < 16; i++) {  // A: 2048 16B chunks
                int c = i * 128 + tid;
                int row = c >> 3, seg = c & 7;
                uint32_t off = (uint32_t)(row & 127) * 128 + seg * 16;
                uint32_t sw = off ^ ((off >> 3) & 0x70);
                cp_async16(smem_u32(st + (row >> 7) * 16384 + sw),
                           Ag + (size_t)row * 2048 + seg * 16);
            }
#pragma unroll
            for (int i = 0; i < 16; i++) {  // B: 2048 16B chunks
                int c = i * 128 + tid;
                int row = c >> 3, seg = c & 7;
                uint32_t off = (uint32_t)row * 128 + seg * 16;
                uint32_t sw = off ^ ((off >> 3) & 0x70);
                cp_async16(smem_u32(st + 32768 + sw),
                           Bg + (size_t)row * 2048 + seg * 16);
            }
            asm volatile("cp.async.commit_group;\n");
            if (kt >= 2) {
                asm volatile("cp.async.wait_group 2;\n");
                mbar_arrive(&bar_full[(kt - 2) % STAGES]);
            }
            if (++s == STAGES) { s = 0; ph ^= 1; }
        }
        asm volatile("cp.async.wait_group 1;\n");
        mbar_arrive(&bar_full[(KT - 2) % STAGES]);
        asm volatile("cp.async.wait_group 0;\n");
        mbar_arrive(&bar_full[(KT - 1) % STAGES]);
    } else if (warp == 4 && lane == 0) {
        // ------------------ MMA issue: single thread ------------------
        int s = 0, ph = 0;
        for (int kt = 0; kt < KT; kt++) {
            mbar_wait(&bar_full[s], (uint32_t)ph);
            asm volatile("fence.proxy.async.shared::cta;" ::: "memory");
            char* st = tiles + s * STAGE_BYTES;
            uint64_t a0 = make_desc(smem_u32(st));
            uint64_t a1 = make_desc(smem_u32(st + 16384));
            uint64_t b0 = make_desc(smem_u32(st + 32768));
            uint64_t b1 = make_desc(smem_u32(st + 32768 + 16384));
#pragma unroll
            for (int ks = 0; ks < 4; ks++) {
                uint32_t en = (kt == 0 && ks == 0) ? 0u : 1u;
                uint64_t ko = (uint64_t)(ks * 2);  // 32 bytes per K-step
                mma_f16_ss(tmem + 0,   a0 + ko, b0 + ko, IDESC_F16_128, en);
                mma_f16_ss(tmem + 128, a0 + ko, b1 + ko, IDESC_F16_128, en);
                mma_f16_ss(tmem + 256, a1 + ko, b0 + ko, IDESC_F16_128, en);
                mma_f16_ss(tmem + 384, a1 + ko, b1 + ko, IDESC_F16_128, en);
            }
            tc_commit(&bar_empty[s]);
            if (++s == STAGES) { s = 0; ph ^= 1; }
        }
        tc_commit(&bar_done);
    }

    __syncthreads();
    mbar_wait(&bar_done, 0);
    asm volatile("tcgen05.fence::after_thread_sync;" ::: "memory");

    // ------------------ epilogue: 8 warps read TMEM ------------------
    const int mhalf = warp >> 2;
    const size_t grow = tileM + mhalf * 128 + (warp & 3) * 32 + lane;
#pragma unroll
    for (int nb = 0; nb < 8; nb++) {
        uint32_t r[32];
        tmem_ld_x32(r, tmem + mhalf * 256 + nb * 32);
        asm volatile("tcgen05.wait::ld.sync.aligned;" ::: "memory");
        const int gc0 = tileN + nb * 32;
        if (OUT_HALF) {
            __half2 h2[16];
#pragma unroll
            for (int i = 0; i < 16; i++)
                h2[i] = __floats2half2_rn(__uint_as_float(r[2 * i]),
                                          __uint_as_float(r[2 * i + 1]));
            int4* dst = reinterpret_cast<int4*>(Ch + grow * N_DIM + gc0);
#pragma unroll
            for (int i = 0; i < 4; i++) dst[i] = reinterpret_cast<int4*>(h2)[i];
        } else {
            float4* dst = reinterpret_cast<float4*>(Cf + grow * N_DIM + gc0);
#pragma unroll
            for (int i = 0; i < 8; i++) {
                float4 v;
                v.x = __uint_as_float(r[4 * i + 0]) + (BIAS ? bias[gc0 + 4 * i + 0] : 0.0f);
                v.y = __uint_as_float(r[4 * i + 1]) + (BIAS ? bias[gc0 + 4 * i + 1] : 0.0f);
                v.z = __uint_as_float(r[4 * i + 2]) + (BIAS ? bias[gc0 + 4 * i + 2] : 0.0f);
                v.w = __uint_as_float(r[4 * i + 3]) + (BIAS ? bias[gc0 + 4 * i + 3] : 0.0f);
                dst[i] = v;
            }
        }
    }

    __syncthreads();
    if (warp == 0) {
        asm volatile("tcgen05.relinquish_alloc_permit.cta_group::1.sync.aligned;");
        asm volatile("tcgen05.dealloc.cta_group::1.sync.aligned.b32 %0, %1;"
                     ::"r"(tmem), "r"(512));
    }

#else  // ----------------- fallback: wmma per 128x128 quadrant -----------------
    using namespace nvcuda;
    constexpr int BK = 32;
    constexpr int LDA = BK + 8;   // 40
    constexpr int LDB = 128 + 8;  // 136

    // dynamic smem layout
    __half (*As)[128][LDA] = reinterpret_cast<__half (*)[128][LDA]>(tiles);
    __half (*Bs)[BK][LDB]  = reinterpret_cast<__half (*)[BK][LDB]>(tiles + 2 * 128 * LDA * 2);
    float (*stage)[256]    = reinterpret_cast<float (*)[256]>(tiles + 2 * 128 * LDA * 2 + 2 * BK * LDB * 2);

    const int wm = warp >> 2;  // 0..1
    const int wn = warp & 3;   // 0..3

    for (int mi = 0; mi < 2; mi++) {
        for (int ni = 0; ni < 2; ni++) {
            const size_t tM = tileM + mi * 128;
            const int tN = tileN + ni * 128;

            wmma::fragment<wmma::accumulator, 16, 16, 16, float> acc[4][2];
#pragma unroll
            for (int i = 0; i < 4; i++)
#pragma unroll
                for (int j = 0; j < 2; j++) wmma::fill_fragment(acc[i][j], 0.0f);

            auto loadTiles = [&](int buf, int k0) {
#pragma unroll
                for (int it = 0; it < 2; it++) {
                    int c = tid + it * 256;
                    int row = c >> 2, seg = c & 3;
                    cp_async16(smem_u32(&As[buf][row][seg * 8]),
                               A + (tM + row) * K_DIM + k0 + seg * 8);
                }
                // B is K-major [N,K]: load Bs[k][n] = Bw[tN+n][k0+k] (transposed load)
#pragma unroll
                for (int it = 0; it < 2; it++) {
                    int c = tid + it * 256;
                    int nrow = c >> 2, seg = c & 3;  // nrow 0..127, seg 0..3 (8 k each)
                    // scalar fill: 8 halves along K for column nrow
                    // use cp.async of 16B along K then transpose in smem? keep simple:
                    // gather 8 halves with one 16B cp.async into a K-major staging? ->
                    // instead store B K-major in smem and use wmma col_major load.
                    cp_async16(smem_u32(reinterpret_cast<__half*>(Bs) +
                                        ((size_t)buf * BK * LDB) + 0) /*unused*/,
                               Bw /*unused*/);
                    (void)nrow; (void)seg;
                }
                asm volatile("cp.async.commit_group;\n");
            };
            (void)loadTiles;

            // Simpler correct fallback: B loaded K-major into smem rows of K,
            // consumed with wmma col_major (B^T). Layout: Bk[n][k] 128x(32+8).
            __half (*Bk)[128][LDA] = reinterpret_cast<__half (*)[128][LDA]>(
                tiles + 2 * 128 * LDA * 2);
            float (*stg)[256] = reinterpret_cast<float (*)[256]>(
                tiles + 4 * 128 * LDA * 2);

            auto loadTiles2 = [&](int buf, int k0) {
#pragma unroll
                for (int it = 0; it < 2; it++) {
                    int c = tid + it * 256;
                    int row = c >> 2, seg = c & 3;
                    cp_async16(smem_u32(&As[buf][row][seg * 8]),
                               A + (tM + row) * K_DIM + k0 + seg * 8);
                }
#pragma unroll
                for (int it = 0; it < 2; it++) {
                    int c = tid + it * 256;
                    int row = c >> 2, seg = c & 3;
                    cp_async16(smem_u32(&Bk[buf][row][seg * 8]),
                               Bw + (size_t)(tN + row) * K_DIM + k0 + seg * 8);
                }
                asm volatile("cp.async.commit_group;\n");
            };

            loadTiles2(0, 0);
            constexpr int KT2 = K_DIM / BK;  // 32
            for (int kt = 0; kt < KT2; ++kt) {
                if (kt + 1 < KT2)
                    loadTiles2((kt + 1) & 1, (kt + 1) * BK);
                else
                    asm volatile("cp.async.commit_group;\n");
                asm volatile("cp.async.wait_group 1;\n");
                __syncthreads();

                const int buf = kt & 1;
#pragma unroll
                for (int kk = 0; kk < BK; kk += 16) {
                    wmma::fragment<wmma::matrix_a, 16, 16, 16, __half, wmma::row_major> af[4];
                    wmma::fragment<wmma::matrix_b, 16, 16, 16, __half, wmma::col_major> bfr[2];
#pragma unroll
                    for (int i = 0; i < 4; i++)
                        wmma::load_matrix_sync(af[i], &As[buf][wm * 64 + i * 16][kk], LDA);
#pragma unroll
                    for (int j = 0; j < 2; j++)
                        wmma::load_matrix_sync(bfr[j], &Bk[buf][wn * 32 + j * 16][kk], LDA);
#pragma unroll
                    for (int i = 0; i < 4; i++)
#pragma unroll
                        for (int j = 0; j < 2; j++)
                            wmma::mma_sync(acc[i][j], af[i], bfr[j], acc[i][j]);
                }
                __syncthreads();
            }

            // epilogue
#pragma unroll
            for (int i = 0; i < 4; i++) {
#pragma unroll
                for (int j = 0; j < 2; j++) {
                    wmma::store_matrix_sync(stg[warp], acc[i][j], 16, wmma::mem_row_major);
                    __syncwarp();
#pragma unroll
                    for (int p = 0; p < 8; p++) {
                        int e = lane + p * 32;
                        int r2 = e >> 4, cc = e & 15;
                        size_t grow2 = tM + wm * 64 + i * 16 + r2;
                        int gcol = tN + wn * 32 + j * 16 + cc;
                        float v = stg[warp][e];
                        if (BIAS) v += bias[gcol];
                        if (OUT_HALF)
                            Ch[grow2 * N_DIM + gcol] = __float2half(v);
                        else
                            Cf[grow2 * N_DIM + gcol] = v;
                    }
                    __syncwarp();
                }
            }
            __syncthreads();
        }
    }
    (void)stage; (void)Bs;
#endif
}

// ---------------------------------------------------------------------------
// Attention over heads: per row b, q/k/v [16,64] fp16 -> softmax(q k^T / 8) v
// Output transposed concat: c[d*16 + h] = o[h][d], fp16. One warp per row.
// ---------------------------------------------------------------------------
__global__ __launch_bounds__(128) void attn_kernel() {
    __shared__ __align__(16) __half sqkv[4][NQKV];
    __shared__ float ssc[4][256];

    const int w = threadIdx.x >> 5;
    const int lane = threadIdx.x & 31;
    const size_t b = (size_t)blockIdx.x * 4 + w;

    const int4* src = reinterpret_cast<const int4*>(g_qkv + b * NQKV);
    int4* dst = reinterpret_cast<int4*>(sqkv[w]);
#pragma unroll
    for (int it = lane; it < 384; it += 32) dst[it] = src[it];
    __syncwarp();

#pragma unroll
    for (int e = lane; e < 256; e += 32) {
        int h = e >> 4, g = e & 15;
        const __half2* qp = reinterpret_cast<const __half2*>(&sqkv[w][h * 64]);
        const __half2* kp = reinterpret_cast<const __half2*>(&sqkv[w][1024 + g * 64]);
        float s = 0.0f;
#pragma unroll
        for (int d2 = 0; d2 < 32; d2++) {
            float2 qf = __half22float2(qp[d2]);
            float2 kf = __half22float2(kp[d2]);
            s = fmaf(qf.x, kf.x, s);
            s = fmaf(qf.y, kf.y, s);
        }
        ssc[w][e] = s * 0.125f;
    }
    __syncwarp();

    if (lane < 16) {
        const int h = lane;
        float m = -1e30f;
#pragma unroll
        for (int g = 0; g < 16; g++) m = fmaxf(m, ssc[w][h * 16 + g]);
        float s = 0.0f;
#pragma unroll
        for (int g = 0; g < 16; g++) {
            float e = __expf(ssc[w][h * 16 + g] - m);
            ssc[w][h * 16 + g] = e;
            s += e;
        }
        float inv = 1.0f / s;
#pragma unroll
        for (int g = 0; g < 16; g++) ssc[w][h * 16 + g] *= inv;
    }
    __syncwarp();

    __half* crow = g_c + b * F_DIM;
#pragma unroll
    for (int c = lane; c < 1024; c += 32) {
        int h = c & 15;
        int d = c >> 4;
        float accv = 0.0f;
#pragma unroll
        for (int g = 0; g < 16; g++)
            accv = fmaf(ssc[w][h * 16 + g], __half2float(sqkv[w][2048 + g * 64 + d]), accv);
        crow[c] = __float2half(accv);
    }
}

// ---------------------------------------------------------------------------
// launch
// ---------------------------------------------------------------------------
extern "C" void kernel_launch(void* const* d_in, const int* in_sizes, int n_in,
                              void* d_out, int out_size) {
    const float* x  = (const float*)d_in[0];
    const float* Wq = (const float*)d_in[1];
    const float* Wk = (const float*)d_in[2];
    const float* Wv = (const float*)d_in[3];
    const float* Wf = (const float*)d_in[4];
    const float* bf = (const float*)d_in[5];
    float* out = (float*)d_out;

    void *p_xh = nullptr, *p_wqkv = nullptr, *p_wf = nullptr, *p_qkv = nullptr,
         *p_c = nullptr;
    cudaGetSymbolAddress(&p_xh, g_xh);
    cudaGetSymbolAddress(&p_wqkv, g_wqkv);
    cudaGetSymbolAddress(&p_wf, g_wf);
    cudaGetSymbolAddress(&p_qkv, g_qkv);
    cudaGetSymbolAddress(&p_c, g_c);

    cudaFuncSetAttribute(tc_gemm<NQKV, true, false>,
                         cudaFuncAttributeMaxDynamicSharedMemorySize, SMEM_DYN);
    cudaFuncSetAttribute(tc_gemm<OUT_N, false, true>,
                         cudaFuncAttributeMaxDynamicSharedMemorySize, SMEM_DYN);

    convert_x_kernel<<<16384, 256>>>(reinterpret_cast<const float4*>(x));
    convert_wqkv_kernel<<<3072, 256>>>(Wq, Wk, Wv);
    convert_wf_kernel<<<1024, 256>>>(Wf);

    // QKV = x @ Wqkv^T   [65536,1024] x [3072,1024]^T
    tc_gemm<NQKV, true, false><<<dim3(NQKV / 256, B_SZ / 256), 256, SMEM_DYN>>>(
        (const __half*)p_xh, (const __half*)p_wqkv, (__half*)p_qkv, nullptr, nullptr);

    // attention over heads -> transposed concat
    attn_kernel<<<B_SZ / 4, 128>>>();

    // out = concat @ Wf^T + bf   [65536,1024] x [1024,1024]^T
    tc_gemm<OUT_N, false, true><<<dim3(OUT_N / 256, B_SZ / 256), 256, SMEM_DYN>>>(
        (const __half*)p_c, (const __half*)p_wf, nullptr, out, bf);
}